// round 9
// baseline (speedup 1.0000x reference)
#include <cuda_runtime.h>
#include <cstdint>

// Problem constants (fixed shapes from the reference setup)
#define NHEAD 8
#define CCH   16          // 2*NHEAD channels into the coverage conv
#define DCH   32          // conv output channels
#define BB    8           // batch
#define TT    256         // time steps
#define HH    16
#define WW    32
#define LL    512         // HH*WW
#define BTN   2048        // BB*TT
#define EPSV  1e-5f

// ---------------- scratch (device globals; no allocations) ----------------
__device__ float g_gate[BB * CCH * TT];          // [b][c][t]
__device__ float g_cum [BTN * CCH * LL];         // [bt][c][l]  exclusive coverage
__device__ float g_cov [BTN * NHEAD * LL];       // [bt][n][l]  pre-BN projected cov
__device__ float g_stats[17];                    // [0..7]=sum, [8..15]=sumsq, [16]=cnt
__device__ unsigned char g_mask[BB * LL];        // canonical uint8 mask (1 = padded)

// ======================================================================
// Kernel 0: canonicalize the key_padding_mask regardless of storage dtype.
// Detection over the first 4096 bytes (safe under every interpretation):
//   int32 bool  -> nonzero bytes only at j%4==0
//   float32 1.0 -> nonzero bytes only at j%4 in {2,3}
//   uint8 bool  -> nonzero bytes spread over all residues
// ======================================================================
__global__ void mask_prep_kernel(const unsigned char* __restrict__ m)
{
    __shared__ int c0, c1, c23;
    const int tid = threadIdx.x;  // 1024 threads
    if (tid == 0) { c0 = 0; c1 = 0; c23 = 0; }
    __syncthreads();
    int l0 = 0, l1 = 0, l23 = 0;
    for (int j = tid; j < BB * LL; j += 1024) {
        unsigned char v = m[j];
        if (v) {
            int r = j & 3;
            if (r == 0) l0++; else if (r == 1) l1++; else l23++;
        }
    }
    if (l0)  atomicAdd(&c0, l0);
    if (l1)  atomicAdd(&c1, l1);
    if (l23) atomicAdd(&c23, l23);
    __syncthreads();
    int dt;  // 0 = uint8, 1 = int32, 2 = float32
    if (c1 == 0 && c23 == 0)      dt = 1;
    else if (c0 == 0)             dt = 2;
    else                          dt = 0;
    for (int j = tid; j < BB * LL; j += 1024) {
        unsigned char r;
        if (dt == 1)      r = (((const int*)m)[j] != 0);
        else if (dt == 2) r = (((const float*)m)[j] != 0.f);
        else              r = (m[j] != 0);
        g_mask[j] = r;
    }
}

// ======================================================================
// Kernel 1: gating network.  One CTA per (b,t) image.
// g = sigmoid(W2 @ meanpool(relu(conv3x3(attns)+b1)) + b2)  -> g_gate[b][c][t]
// ======================================================================
__global__ __launch_bounds__(128) void gate_kernel(
    const float* __restrict__ prev, const float* __restrict__ curr,
    const float* __restrict__ gw1, const float* __restrict__ gb1,
    const float* __restrict__ gw2, const float* __restrict__ gb2)
{
    __shared__ float att[CCH * LL];       // 32 KB raw attn image [c][l]
    __shared__ float wsm[CCH * 9 * 8];    // g_w1 transposed to [c][k][o]
    __shared__ float red[4][8];
    __shared__ float pooled[8];

    const int bt = blockIdx.x;
    const int b  = bt >> 8;
    const int t  = bt & 255;
    const int tid = threadIdx.x;

    // load attns image: prev channels 0..7, curr channels 8..15 (float4)
#pragma unroll
    for (int k = 0; k < 16; k++) {
        int i = tid + k * 128;            // float4 index in [0,2048)
        int c = i >> 7, j = i & 127;
        const float* src = (c < 8)
            ? prev + ((b * 8 + c) * TT + t) * LL
            : curr + ((b * 8 + (c - 8)) * TT + t) * LL;
        ((float4*)att)[i] = ((const float4*)src)[j];
    }
    // g_w1 [o][c][ky][kx] -> wsm[(c*9+k)*8 + o]
    for (int i = tid; i < 1152; i += 128) {
        int o = i / 144, ck = i - o * 144;
        wsm[ck * 8 + o] = gw1[i];
    }
    __syncthreads();

    // thread: 4 consecutive cols in one row, all 8 output channels
    const int row = tid >> 3;
    const int cb  = (tid & 7) * 4;

    float acc[8][4];
#pragma unroll
    for (int o = 0; o < 8; o++)
#pragma unroll
        for (int p = 0; p < 4; p++) acc[o][p] = 0.f;

    for (int c = 0; c < 16; c++) {
#pragma unroll
        for (int ky = 0; ky < 3; ky++) {
            int r = row + ky - 1;
            if ((unsigned)r >= 16u) continue;
            const float* ar = att + c * 512 + r * 32;
            float x[6];
            x[0] = (cb > 0)  ? ar[cb - 1] : 0.f;
            x[1] = ar[cb + 0];
            x[2] = ar[cb + 1];
            x[3] = ar[cb + 2];
            x[4] = ar[cb + 3];
            x[5] = (cb < 28) ? ar[cb + 4] : 0.f;
#pragma unroll
            for (int kx = 0; kx < 3; kx++) {
                const float4* wv = (const float4*)&wsm[(c * 9 + ky * 3 + kx) * 8];
                float4 wA = wv[0], wBv = wv[1];
                float w[8] = {wA.x, wA.y, wA.z, wA.w, wBv.x, wBv.y, wBv.z, wBv.w};
#pragma unroll
                for (int p = 0; p < 4; p++) {
                    float xv = x[kx + p];
#pragma unroll
                    for (int o = 0; o < 8; o++) acc[o][p] = fmaf(w[o], xv, acc[o][p]);
                }
            }
        }
    }

    // bias + relu + spatial sum (for mean pool)
    float rs[8];
#pragma unroll
    for (int o = 0; o < 8; o++) {
        float bo = __ldg(gb1 + o);
        float s = 0.f;
#pragma unroll
        for (int p = 0; p < 4; p++) s += fmaxf(acc[o][p] + bo, 0.f);
        rs[o] = s;
    }
#pragma unroll
    for (int off = 16; off >= 1; off >>= 1)
#pragma unroll
        for (int o = 0; o < 8; o++) rs[o] += __shfl_xor_sync(0xffffffffu, rs[o], off);
    if ((tid & 31) == 0) {
#pragma unroll
        for (int o = 0; o < 8; o++) red[tid >> 5][o] = rs[o];
    }
    __syncthreads();
    if (tid < 8)
        pooled[tid] = (red[0][tid] + red[1][tid] + red[2][tid] + red[3][tid]) * (1.f / 512.f);
    __syncthreads();
    if (tid < 16) {
        float s = __ldg(gb2 + tid);
#pragma unroll
        for (int i = 0; i < 8; i++) s = fmaf(__ldg(gw2 + tid * 8 + i), pooled[i], s);
        g_gate[(b * 16 + tid) * TT + t] = 1.f / (1.f + expf(-s));
    }
}

// ======================================================================
// Kernel 2: gated exclusive cumsum over t.  CTA = (b,c), thread = l.
// g_cum[bt][c][l] = sum_{s<t} gate[b][c][s]*attn[b][c][s][l]
// ======================================================================
__global__ __launch_bounds__(512) void cumsum_kernel(
    const float* __restrict__ prev, const float* __restrict__ curr)
{
    __shared__ float gsh[TT];
    const int bc = blockIdx.x;
    const int b = bc >> 4, c = bc & 15;
    const int l = threadIdx.x;
    if (l < TT) gsh[l] = g_gate[bc * TT + l];
    __syncthreads();

    const float* src = ((c < 8) ? prev + (b * 8 + c) * TT * LL
                                : curr + (b * 8 + (c - 8)) * TT * LL) + l;
    float* dst = g_cum + (b * TT * CCH + c) * LL + l;

    float run = 0.f;
#pragma unroll 1
    for (int t = 0; t < TT; t += 4) {
        float a0 = src[(t + 0) * LL];
        float a1 = src[(t + 1) * LL];
        float a2 = src[(t + 2) * LL];
        float a3 = src[(t + 3) * LL];
        float g0 = gsh[t + 0], g1 = gsh[t + 1], g2 = gsh[t + 2], g3 = gsh[t + 3];
        dst[(t + 0) * (CCH * LL)] = run; run = fmaf(g0, a0, run);
        dst[(t + 1) * (CCH * LL)] = run; run = fmaf(g1, a1, run);
        dst[(t + 2) * (CCH * LL)] = run; run = fmaf(g2, a2, run);
        dst[(t + 3) * (CCH * LL)] = run; run = fmaf(g3, a3, run);
    }
}

// ======================================================================
// Kernel 3: zero the BN stat accumulators (must run each replay)
// ======================================================================
__global__ void init_stats_kernel()
{
    if (threadIdx.x < 17) g_stats[threadIdx.x] = 0.f;
}

// ======================================================================
// Kernel 4: conv5x5 (16->32) + bias + relu + mask + 1x1 proj (32->8)
//           + BN statistics accumulation.  One CTA per (b,t) image.
// smem: padded image [16][20][40], weights [c][ky][kx][32], proj, bias, mask.
// Thread (og=tid&3, pg=tid>>2): 8 output channels x 8 pixels.
// ======================================================================
#define CONV_SMEM_BYTES 104608

__global__ __launch_bounds__(256) void conv_kernel(
    const float* __restrict__ convw, const float* __restrict__ convb,
    const float* __restrict__ projw)
{
    extern __shared__ float sm[];
    float* in_sm = sm;                       // 12800 floats  [16][20][40]
    float* w_sm  = sm + 12800;               // 12800 floats  [c][ky][kx][32]
    float* prj   = sm + 25600;               // 256 floats    [n][32]
    float* cbs   = sm + 25856;               // 32 floats
    float* red   = sm + 25888;               // 8*17 floats
    unsigned char* msk = (unsigned char*)(sm + 26024);  // 512 bytes

    const int bt = blockIdx.x;
    const int b  = bt >> 8;
    const int tid = threadIdx.x;

    // zero padded image (borders stay 0)
#pragma unroll
    for (int i = tid; i < 3200; i += 256)
        ((float4*)in_sm)[i] = make_float4(0.f, 0.f, 0.f, 0.f);
    // conv_w [o][c][ky][kx] -> w_sm[(c*25+k)*32 + o]
    for (int i = tid; i < 12800; i += 256) {
        int o = i / 400, ck = i - o * 400;
        w_sm[ck * 32 + o] = convw[i];
    }
    prj[tid] = __ldg(projw + tid);
    if (tid < 32)  cbs[tid] = __ldg(convb + tid);
    if (tid < 128) ((uint32_t*)msk)[tid] = ((const uint32_t*)(g_mask + b * 512))[tid];
    __syncthreads();

    // fill interior of padded image from g_cum
    const float* img = g_cum + bt * (CCH * LL);
#pragma unroll
    for (int k = 0; k < 16; k++) {
        int i = tid + (k << 8);
        int c = i >> 8, rem = i & 255, r = rem >> 4, j = (rem & 15) << 1;
        float2 v = *(const float2*)(img + c * 512 + r * 32 + j);
        *(float2*)(in_sm + (c * 20 + r + 2) * 40 + 2 + j) = v;
    }
    __syncthreads();

    const int og = tid & 3;            // och group: channels og*8 .. og*8+7
    const int pg = tid >> 2;           // pixel group
    const int row = pg >> 2;
    const int cb  = (pg & 3) << 3;     // 8 consecutive cols

    float acc[8][8];
#pragma unroll
    for (int o = 0; o < 8; o++)
#pragma unroll
        for (int p = 0; p < 8; p++) acc[o][p] = 0.f;

#pragma unroll 1
    for (int c = 0; c < 16; c++) {
#pragma unroll 1
        for (int ky = 0; ky < 5; ky++) {
            const float* xr = in_sm + (c * 20 + row + ky) * 40 + cb;
            float4 xA = *(const float4*)xr;
            float4 xBv = *(const float4*)(xr + 4);
            float4 xC = *(const float4*)(xr + 8);
            float x[12] = {xA.x, xA.y, xA.z, xA.w, xBv.x, xBv.y, xBv.z, xBv.w,
                           xC.x, xC.y, xC.z, xC.w};
            const float* wb = w_sm + (c * 25 + ky * 5) * 32 + (og << 3);
#pragma unroll
            for (int kx = 0; kx < 5; kx++) {
                float4 wA = *(const float4*)(wb + kx * 32);
                float4 wB2 = *(const float4*)(wb + kx * 32 + 4);
                float w[8] = {wA.x, wA.y, wA.z, wA.w, wB2.x, wB2.y, wB2.z, wB2.w};
#pragma unroll
                for (int p = 0; p < 8; p++) {
                    float xv = x[kx + p];
#pragma unroll
                    for (int o = 0; o < 8; o++)
                        acc[o][p] = fmaf(w[o], xv, acc[o][p]);
                }
            }
        }
    }

    // bias + relu
#pragma unroll
    for (int o = 0; o < 8; o++) {
        float bo = cbs[(og << 3) + o];
#pragma unroll
        for (int p = 0; p < 8; p++) acc[o][p] = fmaxf(acc[o][p] + bo, 0.f);
    }

    const int pixb = row * 32 + cb;
    unsigned int mbits = 0;
    float lcnt = 0.f;
#pragma unroll
    for (int p = 0; p < 8; p++) {
        if (msk[pixb + p]) mbits |= (1u << p);
        else               lcnt += 1.f;
    }

    // 1x1 projection 32->8 with cross-og shuffle reduce; mask; stats; store
    float lsum[8], lsq[8];
    float* outp = g_cov + (bt * NHEAD) * LL + pixb;
#pragma unroll
    for (int n = 0; n < 8; n++) {
        float4 pA = *(const float4*)(prj + n * 32 + (og << 3));
        float4 pB = *(const float4*)(prj + n * 32 + (og << 3) + 4);
        float pw[8] = {pA.x, pA.y, pA.z, pA.w, pB.x, pB.y, pB.z, pB.w};
        float v[8];
#pragma unroll
        for (int p = 0; p < 8; p++) {
            float s = 0.f;
#pragma unroll
            for (int o = 0; o < 8; o++) s = fmaf(pw[o], acc[o][p], s);
            s += __shfl_xor_sync(0xffffffffu, s, 1);
            s += __shfl_xor_sync(0xffffffffu, s, 2);
            if (mbits & (1u << p)) s = 0.f;
            v[p] = s;
        }
        lsum[n] = v[0] + v[1] + v[2] + v[3] + v[4] + v[5] + v[6] + v[7];
        lsq[n]  = v[0]*v[0] + v[1]*v[1] + v[2]*v[2] + v[3]*v[3]
                + v[4]*v[4] + v[5]*v[5] + v[6]*v[6] + v[7]*v[7];
        if (og == 0) {
            *(float4*)(outp + n * LL)     = make_float4(v[0], v[1], v[2], v[3]);
            *(float4*)(outp + n * LL + 4) = make_float4(v[4], v[5], v[6], v[7]);
        }
    }

    // reduce stats over og==0 lanes (lanes 0,4,...,28 hold distinct pixel groups;
    // og!=0 lanes hold identical copies and are never combined into lane 0)
#pragma unroll
    for (int off = 4; off <= 16; off <<= 1) {
#pragma unroll
        for (int n = 0; n < 8; n++) {
            lsum[n] += __shfl_xor_sync(0xffffffffu, lsum[n], off);
            lsq[n]  += __shfl_xor_sync(0xffffffffu, lsq[n],  off);
        }
        lcnt += __shfl_xor_sync(0xffffffffu, lcnt, off);
    }
    if ((tid & 31) == 0) {
        float* r = red + (tid >> 5) * 17;
#pragma unroll
        for (int n = 0; n < 8; n++) { r[n] = lsum[n]; r[8 + n] = lsq[n]; }
        r[16] = lcnt;
    }
    __syncthreads();
    if (tid < 17) {
        float s = 0.f;
#pragma unroll
        for (int w2 = 0; w2 < 8; w2++) s += red[w2 * 17 + tid];
        atomicAdd(&g_stats[tid], s);
    }
}

// ======================================================================
// Kernel 5: masked batch-norm + transpose to [b*n][t][l] output layout
// ======================================================================
__global__ __launch_bounds__(256) void final_kernel(
    const float* __restrict__ gamma, const float* __restrict__ beta,
    float* __restrict__ out)
{
    int vid = blockIdx.x * 256 + threadIdx.x;   // float4 id, < 2097152
    int f = vid << 2;
    int b  = f >> 20;
    int nh = (f >> 17) & 7;
    int t  = (f >> 9) & 255;
    int l  = f & 511;

    float cnt  = g_stats[16];
    float mean = g_stats[nh] / cnt;
    float var  = g_stats[8 + nh] / cnt - mean * mean;
    float sc = rsqrtf(var + EPSV) * __ldg(gamma + nh);
    float sh = __ldg(beta + nh) - mean * sc;

    float4 v = *(const float4*)(g_cov + ((((b << 8) + t) * 8 + nh) << 9) + l);
    const unsigned char* mp = g_mask + (b << 9) + l;
    float4 r;
    r.x = mp[0] ? 0.f : fmaf(v.x, sc, sh);
    r.y = mp[1] ? 0.f : fmaf(v.y, sc, sh);
    r.z = mp[2] ? 0.f : fmaf(v.z, sc, sh);
    r.w = mp[3] ? 0.f : fmaf(v.w, sc, sh);
    ((float4*)out)[vid] = r;
}

// ======================================================================
// Launch
// ======================================================================
extern "C" void kernel_launch(void* const* d_in, const int* in_sizes, int n_in,
                              void* d_out, int out_size)
{
    (void)in_sizes; (void)out_size;
    // metadata order: prev_attn, key_padding_mask, [h], curr_attn, [tgt_vocab],
    //                 conv_w, conv_b, proj_w, g_w1, g_b1, g_w2, g_b2, gamma, beta
    // Hedge: if the harness drops python-int scalars, n_in == 12.
    const bool has_scalars = (n_in >= 14);
    const float*         prev  = (const float*)d_in[0];
    const unsigned char* mask  = (const unsigned char*)d_in[1];
    const float*         curr  = (const float*)d_in[has_scalars ? 3 : 2];
    const int            base  = has_scalars ? 5 : 3;
    const float*         convw = (const float*)d_in[base + 0];
    const float*         convb = (const float*)d_in[base + 1];
    const float*         projw = (const float*)d_in[base + 2];
    const float*         gw1   = (const float*)d_in[base + 3];
    const float*         gb1   = (const float*)d_in[base + 4];
    const float*         gw2   = (const float*)d_in[base + 5];
    const float*         gb2   = (const float*)d_in[base + 6];
    const float*         gamma = (const float*)d_in[base + 7];
    const float*         beta  = (const float*)d_in[base + 8];

    cudaFuncSetAttribute(conv_kernel,
                         cudaFuncAttributeMaxDynamicSharedMemorySize,
                         CONV_SMEM_BYTES);

    mask_prep_kernel<<<1, 1024>>>(mask);
    gate_kernel<<<BTN, 128>>>(prev, curr, gw1, gb1, gw2, gb2);
    cumsum_kernel<<<BB * CCH, 512>>>(prev, curr);
    init_stats_kernel<<<1, 32>>>();
    conv_kernel<<<BTN, 256, CONV_SMEM_BYTES>>>(convw, convb, projw);
    final_kernel<<<8192, 256>>>(gamma, beta, (float*)d_out);
}

// round 14
// speedup vs baseline: 1.5140x; 1.5140x over previous
#include <cuda_runtime.h>
#include <cuda_bf16.h>
#include <cstdint>

// Problem constants (fixed shapes from the reference setup)
#define NHEAD 8
#define CCH   16          // 2*NHEAD channels into the coverage conv
#define DCH   32          // conv output channels
#define BB    8           // batch
#define TT    256         // time steps
#define HH    16
#define WW    32
#define LL    512         // HH*WW
#define BTN   2048        // BB*TT
#define EPSV  1e-5f

// ---------------- scratch (device globals; no allocations) ----------------
__device__ float g_gate[BB * CCH * TT];          // [b][c][t]
__device__ float g_cum [BTN * CCH * LL];         // [bt][c][l]  exclusive coverage
__device__ float g_cov [BTN * NHEAD * LL];       // [bt][n][l]  pre-BN projected cov
__device__ float g_stats[17];                    // [0..7]=sum, [8..15]=sumsq, [16]=cnt
__device__ unsigned char g_mask[BB * LL];        // canonical uint8 mask (1 = padded)
// B fragments for mma.sync m16n8k16: hi[8192] then lo[8192] u32 (64KB total)
__device__ uint4 g_wfrag4[4096];

// =====================================================================
// helpers
// =====================================================================
__device__ __forceinline__ uint32_t bf16_split_pack(float x) {
    __nv_bfloat16 h = __float2bfloat16(x);
    __nv_bfloat16 lo = __float2bfloat16(x - __bfloat162float(h));
    return (uint32_t)__bfloat16_as_ushort(h) |
           ((uint32_t)__bfloat16_as_ushort(lo) << 16);
}

// D += A * B  (m16n8k16, row.col, bf16 in, f32 accum)
__device__ __forceinline__ void mma16816(float* d, const uint32_t* a,
                                         const uint32_t* b) {
    asm volatile(
        "mma.sync.aligned.m16n8k16.row.col.f32.bf16.bf16.f32 "
        "{%0,%1,%2,%3}, {%4,%5,%6,%7}, {%8,%9}, {%0,%1,%2,%3};"
        : "+f"(d[0]), "+f"(d[1]), "+f"(d[2]), "+f"(d[3])
        : "r"(a[0]), "r"(a[1]), "r"(a[2]), "r"(a[3]), "r"(b[0]), "r"(b[1]));
}

// ======================================================================
// Kernel 0: canonicalize the key_padding_mask regardless of storage dtype.
// ======================================================================
__global__ void mask_prep_kernel(const unsigned char* __restrict__ m)
{
    __shared__ int c0, c1, c23;
    const int tid = threadIdx.x;  // 1024 threads
    if (tid == 0) { c0 = 0; c1 = 0; c23 = 0; }
    __syncthreads();
    int l0 = 0, l1 = 0, l23 = 0;
    for (int j = tid; j < BB * LL; j += 1024) {
        unsigned char v = m[j];
        if (v) {
            int r = j & 3;
            if (r == 0) l0++; else if (r == 1) l1++; else l23++;
        }
    }
    if (l0)  atomicAdd(&c0, l0);
    if (l1)  atomicAdd(&c1, l1);
    if (l23) atomicAdd(&c23, l23);
    __syncthreads();
    int dt;  // 0 = uint8, 1 = int32, 2 = float32
    if (c1 == 0 && c23 == 0)      dt = 1;
    else if (c0 == 0)             dt = 2;
    else                          dt = 0;
    for (int j = tid; j < BB * LL; j += 1024) {
        unsigned char r;
        if (dt == 1)      r = (((const int*)m)[j] != 0);
        else if (dt == 2) r = (((const float*)m)[j] != 0.f);
        else              r = (m[j] != 0);
        g_mask[j] = r;
    }
}

// ======================================================================
// Kernel 0b: build split-bf16 B fragments for mma.sync m16n8k16 (row.col).
// GEMM: D[px][och] = sum_k A[px][k] * W[och][k], k = c*32 + kk (kk>=25 pad 0).
// Fragment entry i = ((ks*4 + nf)*2 + rg)*32 + lane:
//   n = nf*8 + (lane>>2); k = ks*16 + (lane&3)*2 + rg*8; pair (k, k+1).
//   reg = bf16(W[n][k]) | bf16(W[n][k+1])<<16  (hi array; lo array = residuals)
// ======================================================================
__global__ void weights_prep_kernel(const float* __restrict__ convw)
{
    int i = blockIdx.x * 256 + threadIdx.x;   // 8192 entries
    if (i >= 8192) return;
    const int lane = i & 31;
    const int rg   = (i >> 5) & 1;
    const int nf   = (i >> 6) & 3;
    const int ks   = i >> 8;
    const int n  = (nf << 3) + (lane >> 2);
    const int k0 = (ks << 4) + ((lane & 3) << 1) + (rg << 3);
    const int c  = k0 >> 5;
    const int kk0 = k0 & 31, kk1 = kk0 + 1;
    float w0 = (kk0 < 25) ? convw[(n * 16 + c) * 25 + kk0] : 0.f;
    float w1 = (kk1 < 25) ? convw[(n * 16 + c) * 25 + kk1] : 0.f;
    uint32_t p0 = bf16_split_pack(w0);   // hi low16, lo high16
    uint32_t p1 = bf16_split_pack(w1);
    uint32_t* w = (uint32_t*)g_wfrag4;
    w[i]        = __byte_perm(p0, p1, 0x5410);   // (hi0, hi1)
    w[8192 + i] = __byte_perm(p0, p1, 0x7632);   // (lo0, lo1)
}

// ======================================================================
// Kernel 1: gating network.  One CTA per (b,t) image.  (unchanged)
// ======================================================================
__global__ __launch_bounds__(128) void gate_kernel(
    const float* __restrict__ prev, const float* __restrict__ curr,
    const float* __restrict__ gw1, const float* __restrict__ gb1,
    const float* __restrict__ gw2, const float* __restrict__ gb2)
{
    __shared__ float att[CCH * LL];
    __shared__ float wsm[CCH * 9 * 8];
    __shared__ float red[4][8];
    __shared__ float pooled[8];

    const int bt = blockIdx.x;
    const int b  = bt >> 8;
    const int t  = bt & 255;
    const int tid = threadIdx.x;

#pragma unroll
    for (int k = 0; k < 16; k++) {
        int i = tid + k * 128;
        int c = i >> 7, j = i & 127;
        const float* src = (c < 8)
            ? prev + ((b * 8 + c) * TT + t) * LL
            : curr + ((b * 8 + (c - 8)) * TT + t) * LL;
        ((float4*)att)[i] = ((const float4*)src)[j];
    }
    for (int i = tid; i < 1152; i += 128) {
        int o = i / 144, ck = i - o * 144;
        wsm[ck * 8 + o] = gw1[i];
    }
    __syncthreads();

    const int row = tid >> 3;
    const int cb  = (tid & 7) * 4;

    float acc[8][4];
#pragma unroll
    for (int o = 0; o < 8; o++)
#pragma unroll
        for (int p = 0; p < 4; p++) acc[o][p] = 0.f;

    for (int c = 0; c < 16; c++) {
#pragma unroll
        for (int ky = 0; ky < 3; ky++) {
            int r = row + ky - 1;
            if ((unsigned)r >= 16u) continue;
            const float* ar = att + c * 512 + r * 32;
            float x[6];
            x[0] = (cb > 0)  ? ar[cb - 1] : 0.f;
            x[1] = ar[cb + 0];
            x[2] = ar[cb + 1];
            x[3] = ar[cb + 2];
            x[4] = ar[cb + 3];
            x[5] = (cb < 28) ? ar[cb + 4] : 0.f;
#pragma unroll
            for (int kx = 0; kx < 3; kx++) {
                const float4* wv = (const float4*)&wsm[(c * 9 + ky * 3 + kx) * 8];
                float4 wA = wv[0], wBv = wv[1];
                float w[8] = {wA.x, wA.y, wA.z, wA.w, wBv.x, wBv.y, wBv.z, wBv.w};
#pragma unroll
                for (int p = 0; p < 4; p++) {
                    float xv = x[kx + p];
#pragma unroll
                    for (int o = 0; o < 8; o++) acc[o][p] = fmaf(w[o], xv, acc[o][p]);
                }
            }
        }
    }

    float rs[8];
#pragma unroll
    for (int o = 0; o < 8; o++) {
        float bo = __ldg(gb1 + o);
        float s = 0.f;
#pragma unroll
        for (int p = 0; p < 4; p++) s += fmaxf(acc[o][p] + bo, 0.f);
        rs[o] = s;
    }
#pragma unroll
    for (int off = 16; off >= 1; off >>= 1)
#pragma unroll
        for (int o = 0; o < 8; o++) rs[o] += __shfl_xor_sync(0xffffffffu, rs[o], off);
    if ((tid & 31) == 0) {
#pragma unroll
        for (int o = 0; o < 8; o++) red[tid >> 5][o] = rs[o];
    }
    __syncthreads();
    if (tid < 8)
        pooled[tid] = (red[0][tid] + red[1][tid] + red[2][tid] + red[3][tid]) * (1.f / 512.f);
    __syncthreads();
    if (tid < 16) {
        float s = __ldg(gb2 + tid);
#pragma unroll
        for (int i = 0; i < 8; i++) s = fmaf(__ldg(gw2 + tid * 8 + i), pooled[i], s);
        g_gate[(b * 16 + tid) * TT + t] = 1.f / (1.f + expf(-s));
    }
}

// ======================================================================
// Kernel 2: gated exclusive cumsum over t.  (unchanged)
// ======================================================================
__global__ __launch_bounds__(512) void cumsum_kernel(
    const float* __restrict__ prev, const float* __restrict__ curr)
{
    __shared__ float gsh[TT];
    const int bc = blockIdx.x;
    const int b = bc >> 4, c = bc & 15;
    const int l = threadIdx.x;
    if (l < TT) gsh[l] = g_gate[bc * TT + l];
    __syncthreads();

    const float* src = ((c < 8) ? prev + (b * 8 + c) * TT * LL
                                : curr + (b * 8 + (c - 8)) * TT * LL) + l;
    float* dst = g_cum + (b * TT * CCH + c) * LL + l;

    float run = 0.f;
#pragma unroll 1
    for (int t = 0; t < TT; t += 4) {
        float a0 = src[(t + 0) * LL];
        float a1 = src[(t + 1) * LL];
        float a2 = src[(t + 2) * LL];
        float a3 = src[(t + 3) * LL];
        float g0 = gsh[t + 0], g1 = gsh[t + 1], g2 = gsh[t + 2], g3 = gsh[t + 3];
        dst[(t + 0) * (CCH * LL)] = run; run = fmaf(g0, a0, run);
        dst[(t + 1) * (CCH * LL)] = run; run = fmaf(g1, a1, run);
        dst[(t + 2) * (CCH * LL)] = run; run = fmaf(g2, a2, run);
        dst[(t + 3) * (CCH * LL)] = run; run = fmaf(g3, a3, run);
    }
}

// ======================================================================
// Kernel 3: zero the BN stat accumulators (must run each replay)
// ======================================================================
__global__ void init_stats_kernel()
{
    if (threadIdx.x < 17) g_stats[threadIdx.x] = 0.f;
}

// ======================================================================
// Kernel 4: implicit-GEMM conv5x5 via mma.sync (split-bf16, f32 accum)
//           + bias + relu + mask + 1x1 proj + BN stats.
// One CTA per (b,t) image, 256 threads = 8 warps; warp w owns px [w*64, w*64+64).
// GEMM: D[512 px][32 och], K = 512 (16 ch x 32-padded taps).
// SMEM:
//   0       out_sm  float [512][34]   (69632 B, written after mainloop)
//   69632   img_sm  u32   [16][20][40] packed (hi,lo) bf16   (51200 B)
//   120832  bf_sm   u32   B-frags hi[8192], lo[8192]         (65536 B)
//   186368  prj 1024 | 187392 cbs 128 | 187520 red 544 | 188064 msk 512
// ======================================================================
#define SM_IMG_OFF  69632
#define SM_BF_OFF   120832
#define CONV_SMEM_TOTAL 188608

__global__ __launch_bounds__(256, 1) void conv_mma_kernel(
    const float* __restrict__ convb, const float* __restrict__ projw)
{
    extern __shared__ char smc[];
    float*    out_sm = (float*)smc;                      // [512][34]
    uint32_t* img_sm = (uint32_t*)(smc + SM_IMG_OFF);    // [16][20][40]
    uint32_t* bf_sm  = (uint32_t*)(smc + SM_BF_OFF);     // hi[8192] lo[8192]
    float* prjf = (float*)(smc + 186368);
    float* cbsf = (float*)(smc + 187392);
    float* redf = (float*)(smc + 187520);
    unsigned char* mskb = (unsigned char*)(smc + 188064);

    const int bt = blockIdx.x;
    const int b  = bt >> 8;
    const int tid = threadIdx.x;
    const int wid = tid >> 5;
    const int lane = tid & 31;
    const int gr = lane >> 2;           // fragment row group
    const int gc = (lane & 3) << 1;     // fragment col group (x2)

    // ---- load phase ----
    // zero padded image (borders stay 0)
#pragma unroll
    for (int i = tid; i < 3200; i += 256)
        ((uint4*)img_sm)[i] = make_uint4(0u, 0u, 0u, 0u);
    // B fragments (64KB)
#pragma unroll
    for (int i = tid; i < 4096; i += 256)
        ((uint4*)bf_sm)[i] = g_wfrag4[i];
    prjf[tid] = __ldg(projw + tid);
    if (tid < 32)  cbsf[tid] = __ldg(convb + tid);
    if (tid < 128) ((uint32_t*)mskb)[tid] = ((const uint32_t*)(g_mask + b * 512))[tid];
    __syncthreads();

    // interior: split-bf16 packed values
    const float* img = g_cum + bt * (CCH * LL);
#pragma unroll
    for (int i = tid; i < 8192; i += 256) {
        int c = i >> 9, rem = i & 511, r = rem >> 5, j = rem & 31;
        img_sm[(c * 20 + r + 2) * 40 + (j + 2)] = bf16_split_pack(img[i]);
    }
    __syncthreads();

    // ---- main GEMM loop ----
    float acc[4][4][4];
#pragma unroll
    for (int mf = 0; mf < 4; mf++)
#pragma unroll
        for (int nf = 0; nf < 4; nf++)
#pragma unroll
            for (int j = 0; j < 4; j++) acc[mf][nf][j] = 0.f;

#pragma unroll 1
    for (int ks = 0; ks < 32; ks++) {
        const int c   = ks >> 1;
        const int kkb = (ks & 1) << 4;

        // B fragments for this k-step (conflict-free lane loads)
        uint32_t Bh[4][2], Bl[4][2];
#pragma unroll
        for (int nf = 0; nf < 4; nf++)
#pragma unroll
            for (int rg = 0; rg < 2; rg++) {
                int idx = (((ks * 4 + nf) * 2) + rg) * 32 + lane;
                Bh[nf][rg] = bf_sm[idx];
                Bl[nf][rg] = bf_sm[8192 + idx];
            }

        // per-lane tap offsets for this k-step (k positions gc, gc+1, gc+8, gc+9)
        int off[4]; bool val[4];
#pragma unroll
        for (int j = 0; j < 4; j++) {
            int kk = kkb + gc + ((j & 1) ? 1 : 0) + ((j & 2) ? 8 : 0);
            val[j] = (kk < 25);
            int ky = kk / 5, kx = kk - ky * 5;
            off[j] = ky * 40 + kx;
        }

#pragma unroll
        for (int mf = 0; mf < 4; mf++) {
            const int p0 = (wid << 6) + (mf << 4) + gr;
            const int p1 = p0 + 8;
            const int b0 = (c * 20 + (p0 >> 5)) * 40 + (p0 & 31);
            const int b1 = (c * 20 + (p1 >> 5)) * 40 + (p1 & 31);
            uint32_t v0 = val[0] ? img_sm[b0 + off[0]] : 0u;
            uint32_t v1 = val[1] ? img_sm[b0 + off[1]] : 0u;
            uint32_t v2 = val[0] ? img_sm[b1 + off[0]] : 0u;
            uint32_t v3 = val[1] ? img_sm[b1 + off[1]] : 0u;
            uint32_t v4 = val[2] ? img_sm[b0 + off[2]] : 0u;
            uint32_t v5 = val[3] ? img_sm[b0 + off[3]] : 0u;
            uint32_t v6 = val[2] ? img_sm[b1 + off[2]] : 0u;
            uint32_t v7 = val[3] ? img_sm[b1 + off[3]] : 0u;
            uint32_t Ah[4], Al[4];
            Ah[0] = __byte_perm(v0, v1, 0x5410); Al[0] = __byte_perm(v0, v1, 0x7632);
            Ah[1] = __byte_perm(v2, v3, 0x5410); Al[1] = __byte_perm(v2, v3, 0x7632);
            Ah[2] = __byte_perm(v4, v5, 0x5410); Al[2] = __byte_perm(v4, v5, 0x7632);
            Ah[3] = __byte_perm(v6, v7, 0x5410); Al[3] = __byte_perm(v6, v7, 0x7632);
#pragma unroll
            for (int nf = 0; nf < 4; nf++) {
                mma16816(acc[mf][nf], Ah, Bh[nf]);
                mma16816(acc[mf][nf], Ah, Bl[nf]);
                mma16816(acc[mf][nf], Al, Bh[nf]);
            }
        }
    }

    // ---- bias + relu, scatter to out_sm [px][34] ----
#pragma unroll
    for (int mf = 0; mf < 4; mf++) {
        const int p0 = (wid << 6) + (mf << 4) + gr;
        const int p1 = p0 + 8;
#pragma unroll
        for (int nf = 0; nf < 4; nf++) {
            const int n0 = (nf << 3) + gc;
            float bA = cbsf[n0], bBv = cbsf[n0 + 1];
            float2 w0, w1;
            w0.x = fmaxf(acc[mf][nf][0] + bA,  0.f);
            w0.y = fmaxf(acc[mf][nf][1] + bBv, 0.f);
            w1.x = fmaxf(acc[mf][nf][2] + bA,  0.f);
            w1.y = fmaxf(acc[mf][nf][3] + bBv, 0.f);
            *(float2*)&out_sm[p0 * 34 + n0] = w0;
            *(float2*)&out_sm[p1 * 34 + n0] = w1;
        }
    }
    __syncthreads();

    // ---- epilogue: mask + 1x1 proj + stats (2 px per thread) ----
    float lsum[8] = {0,0,0,0,0,0,0,0}, lsq[8] = {0,0,0,0,0,0,0,0};
    float lcnt = 0.f;
#pragma unroll
    for (int e = 0; e < 2; e++) {
        const int px = (tid << 1) + e;
        float f[32];
#pragma unroll
        for (int q = 0; q < 16; q++) {
            float2 t2 = *(float2*)&out_sm[px * 34 + (q << 1)];
            f[2 * q] = t2.x; f[2 * q + 1] = t2.y;
        }
        const bool pm = (mskb[px] != 0);
        if (!pm) lcnt += 1.f;
        float* outp = g_cov + bt * (NHEAD * LL) + px;
#pragma unroll
        for (int n = 0; n < 8; n++) {
            float s = 0.f;
            const float4* pv = (const float4*)(prjf + n * 32);
#pragma unroll
            for (int og = 0; og < 8; og++) {
                float4 p4 = pv[og];
                s = fmaf(p4.x, f[og * 4 + 0], s);
                s = fmaf(p4.y, f[og * 4 + 1], s);
                s = fmaf(p4.z, f[og * 4 + 2], s);
                s = fmaf(p4.w, f[og * 4 + 3], s);
            }
            if (pm) s = 0.f;
            outp[n * LL] = s;
            lsum[n] += s;
            lsq[n]  += s * s;
        }
    }
#pragma unroll
    for (int off = 16; off >= 1; off >>= 1) {
#pragma unroll
        for (int n = 0; n < 8; n++) {
            lsum[n] += __shfl_xor_sync(0xffffffffu, lsum[n], off);
            lsq[n]  += __shfl_xor_sync(0xffffffffu, lsq[n],  off);
        }
        lcnt += __shfl_xor_sync(0xffffffffu, lcnt, off);
    }
    if (lane == 0) {
        float* rr = redf + wid * 17;
#pragma unroll
        for (int n = 0; n < 8; n++) { rr[n] = lsum[n]; rr[8 + n] = lsq[n]; }
        rr[16] = lcnt;
    }
    __syncthreads();
    if (tid < 17) {
        float s = 0.f;
#pragma unroll
        for (int w = 0; w < 8; w++) s += redf[w * 17 + tid];
        atomicAdd(&g_stats[tid], s);
    }
}

// ======================================================================
// Kernel 5: masked batch-norm + transpose to [b*n][t][l] output layout
// ======================================================================
__global__ __launch_bounds__(256) void final_kernel(
    const float* __restrict__ gamma, const float* __restrict__ beta,
    float* __restrict__ out)
{
    int vid = blockIdx.x * 256 + threadIdx.x;   // float4 id
    int f = vid << 2;
    int b  = f >> 20;
    int nh = (f >> 17) & 7;
    int t  = (f >> 9) & 255;
    int l  = f & 511;

    float cnt  = g_stats[16];
    float mean = g_stats[nh] / cnt;
    float var  = g_stats[8 + nh] / cnt - mean * mean;
    float sc = rsqrtf(var + EPSV) * __ldg(gamma + nh);
    float sh = __ldg(beta + nh) - mean * sc;

    float4 v = *(const float4*)(g_cov + ((((b << 8) + t) * 8 + nh) << 9) + l);
    const unsigned char* mp = g_mask + (b << 9) + l;
    float4 r;
    r.x = mp[0] ? 0.f : fmaf(v.x, sc, sh);
    r.y = mp[1] ? 0.f : fmaf(v.y, sc, sh);
    r.z = mp[2] ? 0.f : fmaf(v.z, sc, sh);
    r.w = mp[3] ? 0.f : fmaf(v.w, sc, sh);
    ((float4*)out)[vid] = r;
}

// ======================================================================
// Launch
// ======================================================================
extern "C" void kernel_launch(void* const* d_in, const int* in_sizes, int n_in,
                              void* d_out, int out_size)
{
    (void)in_sizes; (void)out_size;
    const bool has_scalars = (n_in >= 14);
    const float*         prev  = (const float*)d_in[0];
    const unsigned char* mask  = (const unsigned char*)d_in[1];
    const float*         curr  = (const float*)d_in[has_scalars ? 3 : 2];
    const int            base  = has_scalars ? 5 : 3;
    const float*         convw = (const float*)d_in[base + 0];
    const float*         convb = (const float*)d_in[base + 1];
    const float*         projw = (const float*)d_in[base + 2];
    const float*         gw1   = (const float*)d_in[base + 3];
    const float*         gb1   = (const float*)d_in[base + 4];
    const float*         gw2   = (const float*)d_in[base + 5];
    const float*         gb2   = (const float*)d_in[base + 6];
    const float*         gamma = (const float*)d_in[base + 7];
    const float*         beta  = (const float*)d_in[base + 8];

    cudaFuncSetAttribute(conv_mma_kernel,
                         cudaFuncAttributeMaxDynamicSharedMemorySize,
                         CONV_SMEM_TOTAL);

    mask_prep_kernel<<<1, 1024>>>(mask);
    weights_prep_kernel<<<32, 256>>>(convw);
    gate_kernel<<<BTN, 128>>>(prev, curr, gw1, gb1, gw2, gb2);
    cumsum_kernel<<<BB * CCH, 512>>>(prev, curr);
    init_stats_kernel<<<1, 32>>>();
    conv_mma_kernel<<<BTN, 256, CONV_SMEM_TOTAL>>>(convb, projw);
    final_kernel<<<8192, 256>>>(gamma, beta, (float*)d_out);
}